// round 3
// baseline (speedup 1.0000x reference)
#include <cuda_runtime.h>
#include <cstddef>

// Problem constants (fixed by setup_inputs)
#define B_   32
#define CIN  256
#define COUT 512
#define H_   64
#define W_   64
#define HW   (H_*W_)          // 4096
#define GROUPS 9
#define IN_CPG 28             // 252 channels used, 28 per group
#define OUT_CPG 56            // 504 channels, 56 per group; 504..511 -> group 4

// Scratch: s (B,9,H,W) = 4.5 MiB, W_eff (512,9)
__device__ float g_s[B_ * GROUPS * HW];
__device__ float g_we[COUT * GROUPS];

// ---------------------------------------------------------------------------
// Kernel A: W_eff[o,g] = sum of w_pw[o, 56g..56g+55]; g==4 also adds 504..511
// One warp per (o,g): lanes 0..27 load 2 elements each, shuffle-reduce.
// ---------------------------------------------------------------------------
__global__ __launch_bounds__(256) void shiftconv_weff(const float* __restrict__ w) {
    const int warp = (blockIdx.x * blockDim.x + threadIdx.x) >> 5;
    const int lane = threadIdx.x & 31;
    if (warp >= COUT * GROUPS) return;
    const int o = warp / GROUPS;
    const int g = warp % GROUPS;
    const float* row = w + (size_t)o * COUT;
    float s = 0.f;
    if (lane < IN_CPG)  // 28 lanes active, each sums 2 of the 56 elems
        s = row[g * OUT_CPG + lane] + row[g * OUT_CPG + 28 + lane];
    if (g == 4 && lane < 8)
        s += row[504 + lane];
#pragma unroll
    for (int off = 16; off > 0; off >>= 1)
        s += __shfl_xor_sync(0xffffffffu, s, off);
    if (lane == 0) g_we[warp] = s;
}

// ---------------------------------------------------------------------------
// Kernel B: s[b,g,h,w] = sum_{k<28} x[b, 28g+k, h, w]   (float4 vectorized)
// ---------------------------------------------------------------------------
__global__ void shiftconv_gsum(const float4* __restrict__ x4) {
    int idx = blockIdx.x * blockDim.x + threadIdx.x;     // over B*9*(HW/4)
    const int TOT = B_ * GROUPS * (HW / 4);
    if (idx >= TOT) return;
    int hw4 = idx & (HW / 4 - 1);                        // 0..1023
    int t   = idx >> 10;                                 // b*9+g
    int b = t / GROUPS, g = t % GROUPS;
    const float4* p = x4 + ((size_t)(b * CIN + g * IN_CPG) << 10) + hw4;
    float4 a = make_float4(0.f, 0.f, 0.f, 0.f);
#pragma unroll
    for (int k = 0; k < IN_CPG; k++) {
        float4 v = p[(size_t)k << 10];                   // channel stride = 1024 float4
        a.x += v.x; a.y += v.y; a.z += v.z; a.w += v.w;
    }
    reinterpret_cast<float4*>(g_s)[(size_t)t * (HW / 4) + hw4] = a;
}

// ---------------------------------------------------------------------------
// Kernel C: y[b,o,h,w] = sum_g W_eff[o,g] * s[b,g, h+dy, w+dx]
// Block = (b, 4 h-rows). 256 threads: tx=w (0..63), tg (0..3) -> o quarter.
// f32x2 packed FMA: 2 adjacent o's per 64-bit accumulator. Weights live in
// shared TRANSPOSED [g][o] so one LDS.64 yields the packed weight pair with
// zero pack instructions. s pixel values are duplicated into both halves once.
// ---------------------------------------------------------------------------
#define TH 4
__global__ __launch_bounds__(256) void shiftconv_pw(float* __restrict__ y) {
    __shared__ float w_sh[GROUPS][COUT];                 // transposed, 18.4 KB

    const int b  = blockIdx.x;                           // 0..31
    const int h0 = blockIdx.y * TH;                      // 0,4,...,60
    const int tid = threadIdx.x;

    for (int i = tid; i < COUT * GROUPS; i += 256) {
        int o = i / GROUPS, g = i % GROUPS;              // g_we is [o][g]
        w_sh[g][o] = g_we[i];
    }
    __syncthreads();

    const int tx = tid & 63;                             // w
    const int tg = tid >> 6;                             // 0..3 (o quarter)

    // Load shifted s values for this thread's 4 pixels, duplicate into f32x2
    unsigned long long sv2[GROUPS][TH];
#pragma unroll
    for (int g = 0; g < GROUPS; g++) {
        const int dy = g / 3 - 1;
        const int dx = g % 3 - 1;
        const int wp = tx + dx;
        const bool wok = (unsigned)wp < (unsigned)W_;
        const float* sg = g_s + (size_t)(b * GROUPS + g) * HW;
#pragma unroll
        for (int r = 0; r < TH; r++) {
            const int hp = h0 + r + dy;
            float v = (wok && (unsigned)hp < (unsigned)H_) ? sg[hp * W_ + wp] : 0.f;
            asm("mov.b64 %0, {%1, %1};" : "=l"(sv2[g][r]) : "f"(v));
        }
    }

    float* yb = y + (size_t)b * COUT * HW + (size_t)h0 * W_ + tx;
    const int o_beg = tg * (COUT / 4);                   // 128 o's -> 64 pairs
#pragma unroll 4
    for (int op = 0; op < COUT / 8; op++) {
        const int o = o_beg + op * 2;
        unsigned long long a0 = 0ull, a1 = 0ull, a2 = 0ull, a3 = 0ull;
#pragma unroll
        for (int g = 0; g < GROUPS; g++) {
            // packed weight pair (o, o+1): 8B-aligned LDS.64, warp-broadcast
            unsigned long long w2 =
                *reinterpret_cast<const unsigned long long*>(&w_sh[g][o]);
            asm("fma.rn.f32x2 %0, %1, %2, %0;" : "+l"(a0) : "l"(w2), "l"(sv2[g][0]));
            asm("fma.rn.f32x2 %0, %1, %2, %0;" : "+l"(a1) : "l"(w2), "l"(sv2[g][1]));
            asm("fma.rn.f32x2 %0, %1, %2, %0;" : "+l"(a2) : "l"(w2), "l"(sv2[g][2]));
            asm("fma.rn.f32x2 %0, %1, %2, %0;" : "+l"(a3) : "l"(w2), "l"(sv2[g][3]));
        }
        float* yo0 = yb + (size_t)o * HW;
        float* yo1 = yo0 + HW;
        float lo, hi;
        asm("mov.b64 {%0, %1}, %2;" : "=f"(lo), "=f"(hi) : "l"(a0));
        yo0[0]      = lo;  yo1[0]      = hi;
        asm("mov.b64 {%0, %1}, %2;" : "=f"(lo), "=f"(hi) : "l"(a1));
        yo0[W_]     = lo;  yo1[W_]     = hi;
        asm("mov.b64 {%0, %1}, %2;" : "=f"(lo), "=f"(hi) : "l"(a2));
        yo0[2 * W_] = lo;  yo1[2 * W_] = hi;
        asm("mov.b64 {%0, %1}, %2;" : "=f"(lo), "=f"(hi) : "l"(a3));
        yo0[3 * W_] = lo;  yo1[3 * W_] = hi;
    }
}

// ---------------------------------------------------------------------------
extern "C" void kernel_launch(void* const* d_in, const int* in_sizes, int n_in,
                              void* d_out, int out_size) {
    const float* x = (const float*)d_in[0];
    const float* w = (const float*)d_in[1];
    // Safety: disambiguate by element count if metadata order differs
    if (n_in >= 2 && in_sizes[0] == COUT * COUT) {
        const float* t = x; x = w; w = t;
    }
    float* y = (float*)d_out;

    // 4608 warps, 8 per block
    shiftconv_weff<<<(COUT * GROUPS * 32 + 255) / 256, 256>>>(w);

    const int totB = B_ * GROUPS * (HW / 4);
    shiftconv_gsum<<<(totB + 255) / 256, 256>>>((const float4*)x);

    shiftconv_pw<<<dim3(B_, H_ / TH), 256>>>(y);
}

// round 4
// speedup vs baseline: 1.1453x; 1.1453x over previous
#include <cuda_runtime.h>
#include <cstddef>

// Problem constants (fixed by setup_inputs)
#define B_   32
#define CIN  256
#define COUT 512
#define H_   64
#define W_   64
#define HW   (H_*W_)          // 4096
#define GROUPS 9
#define IN_CPG 28             // 252 channels used, 28 per group
#define OUT_CPG 56            // 504 channels, 56 per group; 504..511 -> group 4

#define GSUM_BLOCKS 1152      // B_*GROUPS*(HW/4) / 256
#define WEFF_BLOCKS 576       // 4608 warps / 8
#define PREP_BLOCKS (GSUM_BLOCKS + WEFF_BLOCKS)

// Scratch: s (B,9,H,W) = 4.5 MiB, W_eff (512,9)
__device__ float g_s[B_ * GROUPS * HW];
__device__ float g_we[COUT * GROUPS];

// ---------------------------------------------------------------------------
// Fused prep kernel.
// Blocks [0, GSUM_BLOCKS):  s[b,g,h,w] = sum_{k<28} x[b, 28g+k, h, w]
// Blocks [GSUM_BLOCKS, ..): W_eff[o,g] = sum w_pw[o, 56g..56g+55] (+504..511 for g=4)
//   (weff is latency-bound; hiding it behind gsum's DRAM traffic is free)
// ---------------------------------------------------------------------------
__global__ __launch_bounds__(256) void shiftconv_prep(const float4* __restrict__ x4,
                                                      const float*  __restrict__ w) {
    const int bx = blockIdx.x;
    if (bx < GSUM_BLOCKS) {
        int idx = bx * 256 + threadIdx.x;                // over B*9*(HW/4)
        int hw4 = idx & (HW / 4 - 1);                    // 0..1023
        int t   = idx >> 10;                             // b*9+g
        int b = t / GROUPS, g = t % GROUPS;
        const float4* p = x4 + ((size_t)(b * CIN + g * IN_CPG) << 10) + hw4;
        float4 a = make_float4(0.f, 0.f, 0.f, 0.f);
#pragma unroll
        for (int k = 0; k < IN_CPG; k++) {
            float4 v = p[(size_t)k << 10];               // channel stride = 1024 float4
            a.x += v.x; a.y += v.y; a.z += v.z; a.w += v.w;
        }
        reinterpret_cast<float4*>(g_s)[(size_t)t * (HW / 4) + hw4] = a;
    } else {
        // warp per (o,g)
        const int warp = (bx - GSUM_BLOCKS) * 8 + (threadIdx.x >> 5);
        const int lane = threadIdx.x & 31;
        const int o = warp / GROUPS;
        const int g = warp % GROUPS;
        const float* row = w + (size_t)o * COUT;
        float s = 0.f;
        if (lane < IN_CPG)
            s = row[g * OUT_CPG + lane] + row[g * OUT_CPG + 28 + lane];
        if (g == 4 && lane < 8)
            s += row[504 + lane];
#pragma unroll
        for (int off = 16; off > 0; off >>= 1)
            s += __shfl_xor_sync(0xffffffffu, s, off);
        if (lane == 0) g_we[warp] = s;
    }
}

// ---------------------------------------------------------------------------
// Kernel C: y[b,o,h,w] = sum_g W_eff[o,g] * s[b,g, h+dy, w+dx]
// Block = (b, h) one output row. 256 threads: w0=(tid&15)*4 (4 consecutive w),
// och=tid>>4 selects 32 o's strided by 16 (o = oo*16 + och).
// f32x2 packed over PIXELS: acc pairs {w0,w0+1},{w0+2,w0+3}. Weights are
// duplicated at store time in shared (w_dup[g][2o]=w_dup[g][2o+1]) so each
// (o,g) is one conflict-free broadcast LDS.64 + 2 FFMA2. One STG.128 per o.
// s row slices staged in shared with zero-padded halo columns.
// ---------------------------------------------------------------------------
__global__ __launch_bounds__(256) void shiftconv_pw(float* __restrict__ y) {
    __shared__ float w_dup[GROUPS][COUT * 2];            // 36,864 B
    __shared__ float s_sh[GROUPS][W_ + 2];               // 2,376 B (halo cols)

    const int b  = blockIdx.x;                           // 0..31
    const int h  = blockIdx.y;                           // 0..63
    const int tid = threadIdx.x;

    // zero s_sh (borders + rows that may be skipped)
    for (int i = tid; i < GROUPS * (W_ + 2); i += 256)
        (&s_sh[0][0])[i] = 0.f;
    // weights: g_we is [o][g]; store duplicated pair per (g,o)
    for (int i = tid; i < COUT * GROUPS; i += 256) {
        int o = i / GROUPS, g = i - o * GROUPS;
        float v = g_we[i];
        w_dup[g][2 * o]     = v;
        w_dup[g][2 * o + 1] = v;
    }
    __syncthreads();

    // stage the single s row each group needs: row h + g/3 - 1
    for (int i = tid; i < GROUPS * W_; i += 256) {
        int g = i >> 6, wc = i & 63;
        int hp = h + g / 3 - 1;
        if ((unsigned)hp < (unsigned)H_)
            s_sh[g][wc + 1] = g_s[((size_t)(b * GROUPS + g) << 12) + (hp << 6) + wc];
    }
    __syncthreads();

    const int w0  = (tid & 15) * 4;
    const int och = tid >> 4;                            // 0..15

    // pack shifted s pixel pairs: idx w0+dx+1 = w0 + g%3
    unsigned long long sv2[GROUPS][2];
#pragma unroll
    for (int g = 0; g < GROUPS; g++) {
        const float* r = &s_sh[g][w0 + (g % 3)];
        asm("mov.b64 %0, {%1, %2};" : "=l"(sv2[g][0]) : "f"(r[0]), "f"(r[1]));
        asm("mov.b64 %0, {%1, %2};" : "=l"(sv2[g][1]) : "f"(r[2]), "f"(r[3]));
    }

    float4* yp = reinterpret_cast<float4*>(
        y + ((size_t)b * COUT + och) * HW + h * W_ + w0);
#pragma unroll 4
    for (int oo = 0; oo < 32; oo++) {
        const int o = oo * 16 + och;
        unsigned long long a0 = 0ull, a1 = 0ull;
#pragma unroll
        for (int g = 0; g < GROUPS; g++) {
            unsigned long long w2 =
                *reinterpret_cast<const unsigned long long*>(&w_dup[g][2 * o]);
            asm("fma.rn.f32x2 %0, %1, %2, %0;" : "+l"(a0) : "l"(w2), "l"(sv2[g][0]));
            asm("fma.rn.f32x2 %0, %1, %2, %0;" : "+l"(a1) : "l"(w2), "l"(sv2[g][1]));
        }
        float4 out;
        asm("mov.b64 {%0, %1}, %2;" : "=f"(out.x), "=f"(out.y) : "l"(a0));
        asm("mov.b64 {%0, %1}, %2;" : "=f"(out.z), "=f"(out.w) : "l"(a1));
        yp[(size_t)oo * 16 * (HW / 4)] = out;            // o stride 16 -> 16*HW floats
    }
}

// ---------------------------------------------------------------------------
extern "C" void kernel_launch(void* const* d_in, const int* in_sizes, int n_in,
                              void* d_out, int out_size) {
    const float* x = (const float*)d_in[0];
    const float* w = (const float*)d_in[1];
    if (n_in >= 2 && in_sizes[0] == COUT * COUT) {       // order safety
        const float* t = x; x = w; w = t;
    }
    float* y = (float*)d_out;

    shiftconv_prep<<<PREP_BLOCKS, 256>>>((const float4*)x, w);
    shiftconv_pw<<<dim3(B_, H_), 256>>>(y);
}

// round 5
// speedup vs baseline: 1.1717x; 1.0230x over previous
#include <cuda_runtime.h>
#include <cstddef>

// Problem constants (fixed by setup_inputs)
#define B_   32
#define CIN  256
#define COUT 512
#define H_   64
#define W_   64
#define HW   (H_*W_)          // 4096
#define GROUPS 9
#define IN_CPG 28             // 252 channels used, 28 per group
#define OUT_CPG 56            // 504 channels, 56 per group; 504..511 -> group 4

#define GSUM_BLOCKS 1152      // B_*GROUPS*(HW/4) / 256
#define WEFF_BLOCKS 576       // 4608 warps / 8
#define PREP_BLOCKS (GSUM_BLOCKS + WEFF_BLOCKS)

#define WSTRIDE 20            // floats per o-row in w_dup2: 9 dup pairs + pad, 80B (16B-aligned)

// Scratch: s (B,9,H,W) = 4.5 MiB, W_eff (512,9)
__device__ float g_s[B_ * GROUPS * HW];
__device__ float g_we[COUT * GROUPS];

// ---------------------------------------------------------------------------
// Fused prep kernel.
// Blocks [0, GSUM_BLOCKS):  s[b,g,h,w] = sum_{k<28} x[b, 28g+k, h, w]
// Blocks [GSUM_BLOCKS, ..): W_eff[o,g] = sum w_pw[o, 56g..56g+55] (+504..511 for g=4)
// ---------------------------------------------------------------------------
__global__ __launch_bounds__(256) void shiftconv_prep(const float4* __restrict__ x4,
                                                      const float*  __restrict__ w) {
    const int bx = blockIdx.x;
    if (bx < GSUM_BLOCKS) {
        int idx = bx * 256 + threadIdx.x;                // over B*9*(HW/4)
        int hw4 = idx & (HW / 4 - 1);                    // 0..1023
        int t   = idx >> 10;                             // b*9+g
        int b = t / GROUPS, g = t % GROUPS;
        const float4* p = x4 + ((size_t)(b * CIN + g * IN_CPG) << 10) + hw4;
        float4 a = make_float4(0.f, 0.f, 0.f, 0.f);
#pragma unroll
        for (int k = 0; k < IN_CPG; k++) {
            float4 v = p[(size_t)k << 10];               // channel stride = 1024 float4
            a.x += v.x; a.y += v.y; a.z += v.z; a.w += v.w;
        }
        reinterpret_cast<float4*>(g_s)[(size_t)t * (HW / 4) + hw4] = a;
    } else {
        // warp per (o,g)
        const int warp = (bx - GSUM_BLOCKS) * 8 + (threadIdx.x >> 5);
        const int lane = threadIdx.x & 31;
        const int o = warp / GROUPS;
        const int g = warp % GROUPS;
        const float* row = w + (size_t)o * COUT;
        float s = 0.f;
        if (lane < IN_CPG)
            s = row[g * OUT_CPG + lane] + row[g * OUT_CPG + 28 + lane];
        if (g == 4 && lane < 8)
            s += row[504 + lane];
#pragma unroll
        for (int off = 16; off > 0; off >>= 1)
            s += __shfl_xor_sync(0xffffffffu, s, off);
        if (lane == 0) g_we[warp] = s;
    }
}

// ---------------------------------------------------------------------------
// Kernel C: y[b,o,h,w] = sum_g W_eff[o,g] * s[b,g, h+dy, w+dx]
// Block = (b, h) one output row. 256 threads: w0=(tid&15)*4, och=tid>>4.
// f32x2 packed over PIXELS. Weights duplicated AND contiguous per o
// (w_dup2[o][20]: pairs for g0..g8 at 8B offsets 0..64), so one o costs
// 4x LDS.128 + 1x LDS.64 (5 wavefronts) instead of 9x LDS.64. L1tex was the
// binding pipe (74%); this cuts LDS wavefronts 1.8x at zero register cost.
// ---------------------------------------------------------------------------
__global__ __launch_bounds__(256) void shiftconv_pw(float* __restrict__ y) {
    __shared__ float w_dup2[COUT * WSTRIDE];             // 40,960 B
    __shared__ float s_sh[GROUPS][W_ + 2];               // 2,376 B (halo cols)

    const int b  = blockIdx.x;                           // 0..31
    const int h  = blockIdx.y;                           // 0..63
    const int tid = threadIdx.x;

    // zero s_sh halo
    for (int i = tid; i < GROUPS * (W_ + 2); i += 256)
        (&s_sh[0][0])[i] = 0.f;
    // weights: g_we is [o][g]; duplicated pair per (o,g), contiguous in o-row
    for (int i = tid; i < COUT * GROUPS; i += 256) {
        int o = i / GROUPS, g = i - o * GROUPS;
        float v = g_we[i];
        w_dup2[o * WSTRIDE + 2 * g]     = v;
        w_dup2[o * WSTRIDE + 2 * g + 1] = v;
    }
    __syncthreads();

    // stage the single s row each group needs: row h + g/3 - 1
    for (int i = tid; i < GROUPS * W_; i += 256) {
        int g = i >> 6, wc = i & 63;
        int hp = h + g / 3 - 1;
        if ((unsigned)hp < (unsigned)H_)
            s_sh[g][wc + 1] = g_s[((size_t)(b * GROUPS + g) << 12) + (hp << 6) + wc];
    }
    __syncthreads();

    const int w0  = (tid & 15) * 4;
    const int och = tid >> 4;                            // 0..15

    // pack shifted s pixel pairs: idx w0+dx+1 = w0 + g%3
    unsigned long long sv2[GROUPS][2];
#pragma unroll
    for (int g = 0; g < GROUPS; g++) {
        const float* r = &s_sh[g][w0 + (g % 3)];
        asm("mov.b64 %0, {%1, %2};" : "=l"(sv2[g][0]) : "f"(r[0]), "f"(r[1]));
        asm("mov.b64 %0, {%1, %2};" : "=l"(sv2[g][1]) : "f"(r[2]), "f"(r[3]));
    }

    float4* yp = reinterpret_cast<float4*>(
        y + ((size_t)b * COUT + och) * HW + h * W_ + w0);
#pragma unroll 4
    for (int oo = 0; oo < 32; oo++) {
        const int o = oo * 16 + och;
        const float* wrow = &w_dup2[o * WSTRIDE];
        // 9 duplicated weight pairs via 4x LDS.128 + 1x LDS.64
        ulonglong2 wA = *reinterpret_cast<const ulonglong2*>(wrow);      // g0,g1
        ulonglong2 wB = *reinterpret_cast<const ulonglong2*>(wrow + 4);  // g2,g3
        ulonglong2 wC = *reinterpret_cast<const ulonglong2*>(wrow + 8);  // g4,g5
        ulonglong2 wD = *reinterpret_cast<const ulonglong2*>(wrow + 12); // g6,g7
        unsigned long long wE =
            *reinterpret_cast<const unsigned long long*>(wrow + 16);     // g8

        unsigned long long a0 = 0ull, a1 = 0ull;
        asm("fma.rn.f32x2 %0, %1, %2, %0;" : "+l"(a0) : "l"(wA.x), "l"(sv2[0][0]));
        asm("fma.rn.f32x2 %0, %1, %2, %0;" : "+l"(a1) : "l"(wA.x), "l"(sv2[0][1]));
        asm("fma.rn.f32x2 %0, %1, %2, %0;" : "+l"(a0) : "l"(wA.y), "l"(sv2[1][0]));
        asm("fma.rn.f32x2 %0, %1, %2, %0;" : "+l"(a1) : "l"(wA.y), "l"(sv2[1][1]));
        asm("fma.rn.f32x2 %0, %1, %2, %0;" : "+l"(a0) : "l"(wB.x), "l"(sv2[2][0]));
        asm("fma.rn.f32x2 %0, %1, %2, %0;" : "+l"(a1) : "l"(wB.x), "l"(sv2[2][1]));
        asm("fma.rn.f32x2 %0, %1, %2, %0;" : "+l"(a0) : "l"(wB.y), "l"(sv2[3][0]));
        asm("fma.rn.f32x2 %0, %1, %2, %0;" : "+l"(a1) : "l"(wB.y), "l"(sv2[3][1]));
        asm("fma.rn.f32x2 %0, %1, %2, %0;" : "+l"(a0) : "l"(wC.x), "l"(sv2[4][0]));
        asm("fma.rn.f32x2 %0, %1, %2, %0;" : "+l"(a1) : "l"(wC.x), "l"(sv2[4][1]));
        asm("fma.rn.f32x2 %0, %1, %2, %0;" : "+l"(a0) : "l"(wC.y), "l"(sv2[5][0]));
        asm("fma.rn.f32x2 %0, %1, %2, %0;" : "+l"(a1) : "l"(wC.y), "l"(sv2[5][1]));
        asm("fma.rn.f32x2 %0, %1, %2, %0;" : "+l"(a0) : "l"(wD.x), "l"(sv2[6][0]));
        asm("fma.rn.f32x2 %0, %1, %2, %0;" : "+l"(a1) : "l"(wD.x), "l"(sv2[6][1]));
        asm("fma.rn.f32x2 %0, %1, %2, %0;" : "+l"(a0) : "l"(wD.y), "l"(sv2[7][0]));
        asm("fma.rn.f32x2 %0, %1, %2, %0;" : "+l"(a1) : "l"(wD.y), "l"(sv2[7][1]));
        asm("fma.rn.f32x2 %0, %1, %2, %0;" : "+l"(a0) : "l"(wE),   "l"(sv2[8][0]));
        asm("fma.rn.f32x2 %0, %1, %2, %0;" : "+l"(a1) : "l"(wE),   "l"(sv2[8][1]));

        float4 out;
        asm("mov.b64 {%0, %1}, %2;" : "=f"(out.x), "=f"(out.y) : "l"(a0));
        asm("mov.b64 {%0, %1}, %2;" : "=f"(out.z), "=f"(out.w) : "l"(a1));
        yp[(size_t)oo * 16 * (HW / 4)] = out;            // o stride 16
    }
}

// ---------------------------------------------------------------------------
extern "C" void kernel_launch(void* const* d_in, const int* in_sizes, int n_in,
                              void* d_out, int out_size) {
    const float* x = (const float*)d_in[0];
    const float* w = (const float*)d_in[1];
    if (n_in >= 2 && in_sizes[0] == COUT * COUT) {       // order safety
        const float* t = x; x = w; w = t;
    }
    float* y = (float*)d_out;

    shiftconv_prep<<<PREP_BLOCKS, 256>>>((const float4*)x, w);
    shiftconv_pw<<<dim3(B_, H_), 256>>>(y);
}